// round 2
// baseline (speedup 1.0000x reference)
#include <cuda_runtime.h>
#include <cuda_bf16.h>
#include <math.h>

// Problem constants (fixed shapes)
#define Bb 64
#define Vv 100000
#define Ff 200000
#define Ee (6 * Ff)          // 1,200,000 adjacency entries
#define VT_STRIDE 192        // per-vertex floats in transposed layout: 3 comps * 64 batches

// -------- device scratch (static; no allocations allowed) --------
__device__ int   g_deg[Vv];
__device__ int   g_rowptr[Vv + 1];
__device__ int   g_cursor[Vv];
__device__ int   g_adj[Ee];
__device__ __align__(16) float g_vT[(size_t)Vv * VT_STRIDE];   // 76.8 MB, layout [v][c][b]
__device__ int   g_blocksums[256];
__device__ float g_accum;
__device__ int   g_faces64;   // 1 if faces buffer is int64, 0 if int32

// -------- 0) detect faces dtype --------
// For int64 data with values < 2^31, every odd 32-bit word (the high half) is 0.
// For int32 data, odd words are random vertex ids in [0,100000); P(all 64 == 0) ~ 1e-320.
__global__ void k_detect(const int* __restrict__ faces_w) {
    if (threadIdx.x == 0 && blockIdx.x == 0) {
        int nz = 0;
        #pragma unroll
        for (int t = 0; t < 64; t++) nz |= faces_w[2 * t + 1];
        g_faces64 = (nz == 0) ? 1 : 0;
        g_accum = 0.0f;
    }
}

// -------- 1) init --------
__global__ void k_init() {
    int idx = blockIdx.x * blockDim.x + threadIdx.x;
    if (idx < Vv) g_deg[idx] = 0;
}

__device__ __forceinline__ void load_face(const int* __restrict__ fw, int f, int w64,
                                          int& i, int& j, int& k) {
    if (w64) {
        i = fw[6 * f + 0];
        j = fw[6 * f + 2];
        k = fw[6 * f + 4];
    } else {
        i = fw[3 * f + 0];
        j = fw[3 * f + 1];
        k = fw[3 * f + 2];
    }
}

// -------- 2) degree count --------
__global__ void k_count(const int* __restrict__ faces_w) {
    int f = blockIdx.x * blockDim.x + threadIdx.x;
    if (f >= Ff) return;
    int w64 = g_faces64;
    int i, j, k;
    load_face(faces_w, f, w64, i, j, k);
    atomicAdd(&g_deg[i], 2);
    atomicAdd(&g_deg[j], 2);
    atomicAdd(&g_deg[k], 2);
}

// -------- 3) scan (two-level) --------
#define SCAN_BS 512
#define SCAN_NB ((Vv + SCAN_BS - 1) / SCAN_BS)   // 196

__global__ void k_scan1() {
    __shared__ int sh[SCAN_BS];
    int tid = threadIdx.x;
    int gid = blockIdx.x * SCAN_BS + tid;
    int val = (gid < Vv) ? g_deg[gid] : 0;
    sh[tid] = val;
    __syncthreads();
    for (int off = 1; off < SCAN_BS; off <<= 1) {
        int t = (tid >= off) ? sh[tid - off] : 0;
        __syncthreads();
        sh[tid] += t;
        __syncthreads();
    }
    if (gid < Vv) g_rowptr[gid] = sh[tid] - val;     // exclusive within block
    if (tid == SCAN_BS - 1) g_blocksums[blockIdx.x] = sh[tid];
}

__global__ void k_scan2() {
    __shared__ int sh[256];
    int tid = threadIdx.x;
    int val = (tid < SCAN_NB) ? g_blocksums[tid] : 0;
    sh[tid] = val;
    __syncthreads();
    for (int off = 1; off < 256; off <<= 1) {
        int t = (tid >= off) ? sh[tid - off] : 0;
        __syncthreads();
        sh[tid] += t;
        __syncthreads();
    }
    g_blocksums[tid] = sh[tid] - val;                // exclusive block offsets
}

__global__ void k_scan3() {
    int gid = blockIdx.x * blockDim.x + threadIdx.x;
    if (gid < Vv) {
        int r = g_rowptr[gid] + g_blocksums[gid / SCAN_BS];
        g_rowptr[gid] = r;
        g_cursor[gid] = r;
    }
    if (gid == 0) g_rowptr[Vv] = Ee;
}

// -------- 4) CSR fill --------
__global__ void k_fill(const int* __restrict__ faces_w) {
    int f = blockIdx.x * blockDim.x + threadIdx.x;
    if (f >= Ff) return;
    int w64 = g_faces64;
    int i, j, k;
    load_face(faces_w, f, w64, i, j, k);
    int p;
    p = atomicAdd(&g_cursor[i], 2); g_adj[p] = j; g_adj[p + 1] = k;
    p = atomicAdd(&g_cursor[j], 2); g_adj[p] = i; g_adj[p + 1] = k;
    p = atomicAdd(&g_cursor[k], 2); g_adj[p] = j; g_adj[p + 1] = i;
}

// -------- 5) transpose verts [B][V][3] -> vT [V][3][B] --------
// Tile: 32 vertices x 64 batches x 3 comps = 6144 floats per block.
#define TP_VT 32
__global__ void k_transpose(const float* __restrict__ verts) {
    __shared__ float sh[TP_VT * 3 * 65];   // [rem=v*3+c][b], padded to 65 to kill bank conflicts
    int t = threadIdx.x;                   // 256 threads
    int v0 = blockIdx.x * TP_VT;           // V = 100000 = 32 * 3125, exact

    #pragma unroll
    for (int it = 0; it < 24; it++) {
        int l = it * 256 + t;
        int b = l / 96;
        int rem = l - b * 96;
        float val = verts[(size_t)b * (Vv * 3) + (size_t)v0 * 3 + rem];
        sh[rem * 65 + b] = val;
    }
    __syncthreads();

    float* out = g_vT + (size_t)v0 * VT_STRIDE;
    #pragma unroll
    for (int it = 0; it < 24; it++) {
        int o = it * 256 + t;
        int v = o / 192;
        int r = o - v * 192;
        int c = r >> 6;
        int b = r & 63;
        out[o] = sh[(v * 3 + c) * 65 + b];
    }
}

// -------- 6) gather + norm + reduce : one warp per vertex, lane owns 2 batches --------
#define GATHER_WARPS 8
__global__ void __launch_bounds__(256) k_gather() {
    int lane = threadIdx.x & 31;
    int wid  = threadIdx.x >> 5;
    int v    = blockIdx.x * GATHER_WARPS + wid;

    float nsum = 0.0f;
    if (v < Vv) {
        const float2* vt2 = (const float2*)g_vT;
        int s = g_rowptr[v];
        int e = g_rowptr[v + 1];

        float ax0 = 0.f, ax1 = 0.f, ay0 = 0.f, ay1 = 0.f, az0 = 0.f, az1 = 0.f;
        for (int t = s; t < e; t++) {
            int u = __ldg(&g_adj[t]);                 // warp-uniform broadcast
            const float2* p = vt2 + (size_t)u * 96;   // u * 192 floats / 2
            float2 x = __ldg(&p[lane]);
            float2 y = __ldg(&p[32 + lane]);
            float2 z = __ldg(&p[64 + lane]);
            ax0 += x.x; ax1 += x.y;
            ay0 += y.x; ay1 += y.y;
            az0 += z.x; az1 += z.y;
        }

        const float2* pc = vt2 + (size_t)v * 96;
        float2 cx = pc[lane];
        float2 cy = pc[32 + lane];
        float2 cz = pc[64 + lane];
        float invd = 1.0f / fmaxf((float)g_deg[v], 1.0f);

        float dx0 = cx.x - ax0 * invd, dy0 = cy.x - ay0 * invd, dz0 = cz.x - az0 * invd;
        float dx1 = cx.y - ax1 * invd, dy1 = cy.y - ay1 * invd, dz1 = cz.y - az1 * invd;
        nsum = sqrtf(dx0 * dx0 + dy0 * dy0 + dz0 * dz0)
             + sqrtf(dx1 * dx1 + dy1 * dy1 + dz1 * dz1);
    }

    // warp reduce
    #pragma unroll
    for (int off = 16; off > 0; off >>= 1)
        nsum += __shfl_xor_sync(0xFFFFFFFFu, nsum, off);

    __shared__ float warpsum[GATHER_WARPS];
    if (lane == 0) warpsum[wid] = nsum;
    __syncthreads();
    if (wid == 0) {
        float bsum = (lane < GATHER_WARPS) ? warpsum[lane] : 0.0f;
        #pragma unroll
        for (int off = 4; off > 0; off >>= 1)
            bsum += __shfl_xor_sync(0xFFFFFFFFu, bsum, off);
        if (lane == 0) atomicAdd(&g_accum, bsum);
    }
}

// -------- 7) finalize --------
__global__ void k_finalize(float* __restrict__ out) {
    out[0] = g_accum * (1.0f / ((float)Bb * (float)Vv));
}

extern "C" void kernel_launch(void* const* d_in, const int* in_sizes, int n_in,
                              void* d_out, int out_size) {
    const float* verts   = (const float*)d_in[0];   // (64, 100000, 3) f32
    const int*   faces_w = (const int*)d_in[1];     // (200000, 3) int32 OR int64 (detected)
    float* out = (float*)d_out;

    (void)in_sizes; (void)n_in; (void)out_size;

    k_detect<<<1, 32>>>(faces_w);
    k_init<<<(Vv + 255) / 256, 256>>>();
    k_count<<<(Ff + 255) / 256, 256>>>(faces_w);
    k_scan1<<<SCAN_NB, SCAN_BS>>>();
    k_scan2<<<1, 256>>>();
    k_scan3<<<(Vv + 255) / 256, 256>>>();
    k_fill<<<(Ff + 255) / 256, 256>>>(faces_w);
    k_transpose<<<Vv / TP_VT, 256>>>(verts);
    k_gather<<<(Vv + GATHER_WARPS - 1) / GATHER_WARPS, 256>>>();
    k_finalize<<<1, 1>>>(out);
}

// round 4
// speedup vs baseline: 1.0876x; 1.0876x over previous
#include <cuda_runtime.h>
#include <cuda_fp16.h>
#include <math.h>

// Problem constants (fixed shapes)
#define Bb 64
#define Vv 100000
#define Ff 200000
#define Ee (6 * Ff)          // 1,200,000 adjacency entries
#define VT_STRIDE 192        // per-vertex halves: 3 comps * 64 batches

// -------- device scratch (static; no allocations allowed) --------
__device__ int    g_deg[Vv];
__device__ int    g_rowptr[Vv + 1];
__device__ int    g_cursor[Vv];
__device__ int    g_adj[Ee];
__device__ __align__(16) __half g_vT[(size_t)Vv * VT_STRIDE];   // 38.4 MB, layout [v][c][b] fp16
__device__ int    g_blocksums[256];
__device__ float  g_accum;
__device__ int    g_faces64;   // 1 if faces buffer is int64, 0 if int32

// -------- 1) init degrees + detect faces dtype + clear accum --------
// int64 values < 2^31 -> every odd 32-bit word is 0. int32 random ids -> P(all 64 odd words==0)~0.
__global__ void k_init(const int* __restrict__ faces_w) {
    int idx = blockIdx.x * blockDim.x + threadIdx.x;
    if (idx < Vv) g_deg[idx] = 0;
    if (idx == 0) {
        int nz = 0;
        #pragma unroll
        for (int t = 0; t < 64; t++) nz |= faces_w[2 * t + 1];
        g_faces64 = (nz == 0) ? 1 : 0;
        g_accum = 0.0f;
    }
}

__device__ __forceinline__ void load_face(const int* __restrict__ fw, int f, int w64,
                                          int& i, int& j, int& k) {
    if (w64) {
        i = fw[6 * f + 0];
        j = fw[6 * f + 2];
        k = fw[6 * f + 4];
    } else {
        i = fw[3 * f + 0];
        j = fw[3 * f + 1];
        k = fw[3 * f + 2];
    }
}

// -------- 2) degree count --------
__global__ void k_count(const int* __restrict__ faces_w) {
    int f = blockIdx.x * blockDim.x + threadIdx.x;
    if (f >= Ff) return;
    int w64 = g_faces64;
    int i, j, k;
    load_face(faces_w, f, w64, i, j, k);
    atomicAdd(&g_deg[i], 2);
    atomicAdd(&g_deg[j], 2);
    atomicAdd(&g_deg[k], 2);
}

// -------- 3) scan (two-level, warp-shuffle based) --------
#define SCAN_BS 512
#define SCAN_NB ((Vv + SCAN_BS - 1) / SCAN_BS)   // 196

__global__ void k_scan1() {
    __shared__ int wsum[16];
    int tid = threadIdx.x, lane = tid & 31, w = tid >> 5;
    int gid = blockIdx.x * SCAN_BS + tid;
    int val = (gid < Vv) ? g_deg[gid] : 0;
    int x = val;
    #pragma unroll
    for (int off = 1; off < 32; off <<= 1) {
        int y = __shfl_up_sync(0xFFFFFFFFu, x, off);
        if (lane >= off) x += y;
    }
    if (lane == 31) wsum[w] = x;
    __syncthreads();
    if (w == 0) {
        int s = (lane < 16) ? wsum[lane] : 0;
        #pragma unroll
        for (int off = 1; off < 16; off <<= 1) {
            int y = __shfl_up_sync(0xFFFFFFFFu, s, off);
            if (lane >= off) s += y;
        }
        if (lane < 16) wsum[lane] = s;
    }
    __syncthreads();
    int base = (w > 0) ? wsum[w - 1] : 0;
    int incl = base + x;
    if (gid < Vv) g_rowptr[gid] = incl - val;        // exclusive
    if (tid == SCAN_BS - 1) g_blocksums[blockIdx.x] = incl;
}

__global__ void k_scan2() {
    __shared__ int wsum[8];
    int tid = threadIdx.x, lane = tid & 31, w = tid >> 5;   // 256 threads
    int val = (tid < SCAN_NB) ? g_blocksums[tid] : 0;
    int x = val;
    #pragma unroll
    for (int off = 1; off < 32; off <<= 1) {
        int y = __shfl_up_sync(0xFFFFFFFFu, x, off);
        if (lane >= off) x += y;
    }
    if (lane == 31) wsum[w] = x;
    __syncthreads();
    if (w == 0) {
        int s = (lane < 8) ? wsum[lane] : 0;
        #pragma unroll
        for (int off = 1; off < 8; off <<= 1) {
            int y = __shfl_up_sync(0xFFFFFFFFu, s, off);
            if (lane >= off) s += y;
        }
        if (lane < 8) wsum[lane] = s;
    }
    __syncthreads();
    int base = (w > 0) ? wsum[w - 1] : 0;
    g_blocksums[tid] = base + x - val;                // exclusive block offsets
}

__global__ void k_scan3() {
    int gid = blockIdx.x * blockDim.x + threadIdx.x;
    if (gid < Vv) {
        int r = g_rowptr[gid] + g_blocksums[gid / SCAN_BS];
        g_rowptr[gid] = r;
        g_cursor[gid] = r;
    }
    if (gid == 0) g_rowptr[Vv] = Ee;
}

// -------- 4) CSR fill --------
__global__ void k_fill(const int* __restrict__ faces_w) {
    int f = blockIdx.x * blockDim.x + threadIdx.x;
    if (f >= Ff) return;
    int w64 = g_faces64;
    int i, j, k;
    load_face(faces_w, f, w64, i, j, k);
    int p;
    p = atomicAdd(&g_cursor[i], 2); g_adj[p] = j; g_adj[p + 1] = k;
    p = atomicAdd(&g_cursor[j], 2); g_adj[p] = i; g_adj[p + 1] = k;
    p = atomicAdd(&g_cursor[k], 2); g_adj[p] = j; g_adj[p + 1] = i;
}

// -------- 5) transpose verts [B][V][3] f32 -> vT [V][3][B] fp16 --------
// Tile: 32 vertices x 64 batches x 3 comps per block.
#define TP_VT 32
__global__ void k_transpose(const float* __restrict__ verts) {
    __shared__ float sh[TP_VT * 3 * 65];   // [rem=v*3+c][b], padded 65 to kill bank conflicts
    int t = threadIdx.x;                   // 256 threads
    int v0 = blockIdx.x * TP_VT;           // V = 100000 = 32 * 3125, exact

    // load: linear l -> b = l/96, rem = l%96 ; coalesced 384B runs per b
    #pragma unroll
    for (int it = 0; it < 24; it++) {
        int l = it * 256 + t;
        int b = l / 96;
        int rem = l - b * 96;
        float val = verts[(size_t)b * (Vv * 3) + (size_t)v0 * 3 + rem];
        sh[rem * 65 + b] = val;
    }
    __syncthreads();

    // store: 32 verts * 96 half2 = 3072 half2 per block; contiguous output
    __half2* out = (__half2*)(g_vT + (size_t)v0 * VT_STRIDE);
    #pragma unroll
    for (int it = 0; it < 12; it++) {
        int o = it * 256 + t;              // half2 index within tile
        int v = o / 96;
        int r = o - v * 96;
        int c = r >> 5;                    // component
        int bp = r & 31;                   // batch pair
        float f0 = sh[(v * 3 + c) * 65 + 2 * bp];
        float f1 = sh[(v * 3 + c) * 65 + 2 * bp + 1];
        out[o] = __floats2half2_rn(f0, f1);
    }
}

// -------- 6) gather + norm + reduce : one warp per vertex, lane owns 2 batches --------
#define GATHER_WARPS 8
__global__ void __launch_bounds__(256) k_gather() {
    int lane = threadIdx.x & 31;
    int wid  = threadIdx.x >> 5;
    int v    = blockIdx.x * GATHER_WARPS + wid;

    float nsum = 0.0f;
    if (v < Vv) {
        const __half2* vt2 = (const __half2*)g_vT;   // per-vertex stride 96 half2
        int s = g_rowptr[v];
        int e = g_rowptr[v + 1];

        float ax0 = 0.f, ax1 = 0.f, ay0 = 0.f, ay1 = 0.f, az0 = 0.f, az1 = 0.f;
        for (int t = s; t < e; t++) {
            int u = __ldg(&g_adj[t]);                   // warp-uniform broadcast
            const __half2* p = vt2 + (size_t)u * 96;
            float2 x = __half22float2(__ldg(&p[lane]));
            float2 y = __half22float2(__ldg(&p[32 + lane]));
            float2 z = __half22float2(__ldg(&p[64 + lane]));
            ax0 += x.x; ax1 += x.y;
            ay0 += y.x; ay1 += y.y;
            az0 += z.x; az1 += z.y;
        }

        const __half2* pc = vt2 + (size_t)v * 96;
        float2 cx = __half22float2(pc[lane]);
        float2 cy = __half22float2(pc[32 + lane]);
        float2 cz = __half22float2(pc[64 + lane]);
        float invd = 1.0f / fmaxf((float)g_deg[v], 1.0f);

        float dx0 = cx.x - ax0 * invd, dy0 = cy.x - ay0 * invd, dz0 = cz.x - az0 * invd;
        float dx1 = cx.y - ax1 * invd, dy1 = cy.y - ay1 * invd, dz1 = cz.y - az1 * invd;
        nsum = sqrtf(dx0 * dx0 + dy0 * dy0 + dz0 * dz0)
             + sqrtf(dx1 * dx1 + dy1 * dy1 + dz1 * dz1);
    }

    // warp reduce
    #pragma unroll
    for (int off = 16; off > 0; off >>= 1)
        nsum += __shfl_xor_sync(0xFFFFFFFFu, nsum, off);

    __shared__ float warpsum[GATHER_WARPS];
    if (lane == 0) warpsum[wid] = nsum;
    __syncthreads();
    if (wid == 0) {
        float bsum = (lane < GATHER_WARPS) ? warpsum[lane] : 0.0f;
        #pragma unroll
        for (int off = 4; off > 0; off >>= 1)
            bsum += __shfl_xor_sync(0xFFFFFFFFu, bsum, off);
        if (lane == 0) atomicAdd(&g_accum, bsum);
    }
}

// -------- 7) finalize --------
__global__ void k_finalize(float* __restrict__ out) {
    out[0] = g_accum * (1.0f / ((float)Bb * (float)Vv));
}

extern "C" void kernel_launch(void* const* d_in, const int* in_sizes, int n_in,
                              void* d_out, int out_size) {
    const float* verts   = (const float*)d_in[0];   // (64, 100000, 3) f32
    const int*   faces_w = (const int*)d_in[1];     // (200000, 3) int32 OR int64 (detected)
    float* out = (float*)d_out;

    (void)in_sizes; (void)n_in; (void)out_size;

    k_init<<<(Vv + 255) / 256, 256>>>(faces_w);
    k_count<<<(Ff + 255) / 256, 256>>>(faces_w);
    k_scan1<<<SCAN_NB, SCAN_BS>>>();
    k_scan2<<<1, 256>>>();
    k_scan3<<<(Vv + 255) / 256, 256>>>();
    k_fill<<<(Ff + 255) / 256, 256>>>(faces_w);
    k_transpose<<<Vv / TP_VT, 256>>>(verts);
    k_gather<<<(Vv + GATHER_WARPS - 1) / GATHER_WARPS, 256>>>();
    k_finalize<<<1, 1>>>(out);
}